// round 15
// baseline (speedup 1.0000x reference)
#include <cuda_runtime.h>
#include <cuda_bf16.h>

#define TOTAL_N 1000000
#define DIM     128
#define BATCH   4096
#define WIN     256

__global__ __launch_bounds__(256)
void coord_pool_kernel(const float* __restrict__ mu,
                       const float* __restrict__ sigma,
                       const float* __restrict__ params,
                       float* __restrict__ out,
                       int write_starts)
{
    __shared__ float  sw[WIN];         // normalized weights
    __shared__ float  warpsum[8];
    __shared__ float  s_den;
    __shared__ float4 red4[8 * DIM / 4];

    const int b    = blockIdx.x;
    const int tid  = threadIdx.x;
    const int lane = tid & 31;
    const int wid  = tid >> 5;

    // ---- ref-faithful f32 chain (LOAD-BEARING: do not alter rounding) ----
    const float center_f = __fmul_rn(mu[b], (float)(TOTAL_N - 1));
    float startf = __fadd_rn(center_f, -(float)(WIN / 2));
    startf = fminf(fmaxf(startf, 0.0f), (float)(TOTAL_N - WIN));
    const int start = (int)startf;

    const float sf  = __fadd_rn(sigma[b], 1e-6f);
    const float den = __fmul_rn(2.0f, __fmul_rn(sf, sf));

    // ---- weights: 1 per thread, f32 (arg bit-identical to R13/R14) ----
    float e0, partial;
    {
        const float d0 = __fadd_rn((float)(start + tid), -center_f);
        const float a0 = __fdiv_rn(-__fmul_rn(d0, d0), den);
        e0 = expf(a0);
        partial = e0;
    }
    #pragma unroll
    for (int o = 16; o > 0; o >>= 1)
        partial += __shfl_xor_sync(0xffffffff, partial, o);
    if (lane == 0) warpsum[wid] = partial;
    __syncthreads();
    if (tid == 0) {
        float t = warpsum[0];
        #pragma unroll
        for (int i = 1; i < 8; i++) t += warpsum[i];
        s_den = t + 1e-6f;
    }
    __syncthreads();
    sw[tid] = __fdiv_rn(e0, s_den);
    __syncthreads();

    // ---- gather-reduce: warp `wid` owns rows wid, wid+8, ... (32 rows) ----
    // 32 lanes x float4 = full 512B row per warp-load; unroll 8 -> MLP=8.
    const float4* __restrict__ p4 = (const float4*)params;
    const size_t rowbase = (size_t)start * (DIM / 4);

    float4 acc = make_float4(0.f, 0.f, 0.f, 0.f);
    #pragma unroll 8
    for (int w = wid; w < WIN; w += 8) {
        const float4 v = __ldg(&p4[rowbase + (size_t)w * (DIM / 4) + lane]);
        const float wt = sw[w];
        acc.x = fmaf(wt, v.x, acc.x);
        acc.y = fmaf(wt, v.y, acc.y);
        acc.z = fmaf(wt, v.z, acc.z);
        acc.w = fmaf(wt, v.w, acc.w);
    }

    red4[wid * 32 + lane] = acc;       // red[wid*128 + col]
    __syncthreads();

    if (tid < DIM) {
        const float* red = (const float*)red4;
        float r = red[tid];
        #pragma unroll
        for (int i = 1; i < 8; i++) r += red[i * DIM + tid];
        out[(size_t)b * DIM + tid] = r;
    }

    if (write_starts && tid == 0)
        out[(size_t)BATCH * DIM + b] = (float)start;
}

extern "C" void kernel_launch(void* const* d_in, const int* in_sizes, int n_in,
                              void* d_out, int out_size) {
    int big = 0;
    for (int i = 1; i < n_in; i++)
        if (in_sizes[i] > in_sizes[big]) big = i;

    const float* params = (const float*)d_in[big];
    const float* mu = nullptr;
    const float* sigma = nullptr;
    for (int i = 0; i < n_in; i++) {
        if (i == big) continue;
        if (mu == nullptr) mu = (const float*)d_in[i];
        else if (sigma == nullptr) sigma = (const float*)d_in[i];
    }

    float* out = (float*)d_out;
    const int write_starts = (out_size >= BATCH * DIM + BATCH) ? 1 : 0;

    coord_pool_kernel<<<BATCH, 256>>>(mu, sigma, params, out, write_starts);
}